// round 1
// baseline (speedup 1.0000x reference)
#include <cuda_runtime.h>
#include <math.h>

// Problem constants
#define BATCH 2
#define TT    2048
#define CC    1024
#define NH    16
#define HD    64    // head size
#define BQ    64    // q/k tile in attention

// Device-global scratch (allocation-free rule): Q/K/V in [B,H,T,D], Y in [B,T,C]
__device__ float g_q[BATCH * NH * TT * HD];
__device__ float g_k[BATCH * NH * TT * HD];
__device__ float g_v[BATCH * NH * TT * HD];
__device__ float g_y[BATCH * TT * CC];

// ---------------------------------------------------------------------------
// SGEMM: out = A[M,K] @ W[K,N] + bias[N]
// MODE 0: A = x (param), scatter epilogue -> g_q/g_k/g_v (q scaled by 0.125)
// MODE 1: A = g_y (internal), dense epilogue -> out
// BM=BN=128, BK=8, TM=TN=8, 256 threads. All dims divisible -> no bounds checks.
// ---------------------------------------------------------------------------
template <int MODE>
__global__ void __launch_bounds__(256) sgemm_kernel(
    const float* __restrict__ A_in,
    const float* __restrict__ W,
    const float* __restrict__ bias,
    float* __restrict__ out,
    int M, int N, int K)
{
    constexpr int BM = 128, BN = 128, BK = 8, TM = 8, TN = 8;
    __shared__ float As[BK][BM];
    __shared__ float Bs[BK][BN];

    const int tid = threadIdx.x;
    const int cRow = blockIdx.y;   // block row  (M)
    const int cCol = blockIdx.x;   // block col  (N)

    const int threadCol = tid % (BN / TN);  // 0..15
    const int threadRow = tid / (BN / TN);  // 0..15

    // A tile loader: 128 rows x 8 cols, one float4 per thread
    const int innerRowA = tid >> 1;          // 0..127
    const int innerColA = (tid & 1) * 4;     // 0 or 4
    // B tile loader: 8 rows x 128 cols, one float4 per thread
    const int innerRowB = tid >> 5;          // 0..7
    const int innerColB = (tid & 31) * 4;    // 0..124

    const float* A = (MODE == 1) ? g_y : A_in;
    const float* Ap = A + (size_t)cRow * BM * K;
    const float* Bp = W + (size_t)cCol * BN;

    float acc[TM][TN];
    #pragma unroll
    for (int i = 0; i < TM; i++)
        #pragma unroll
        for (int j = 0; j < TN; j++) acc[i][j] = 0.f;

    for (int k0 = 0; k0 < K; k0 += BK) {
        float4 a4 = *(const float4*)(Ap + (size_t)innerRowA * K + k0 + innerColA);
        As[innerColA + 0][innerRowA] = a4.x;
        As[innerColA + 1][innerRowA] = a4.y;
        As[innerColA + 2][innerRowA] = a4.z;
        As[innerColA + 3][innerRowA] = a4.w;
        *(float4*)&Bs[innerRowB][innerColB] =
            *(const float4*)(Bp + (size_t)(k0 + innerRowB) * N + innerColB);
        __syncthreads();

        #pragma unroll
        for (int k = 0; k < BK; k++) {
            float4 m0 = *(const float4*)&As[k][threadRow * TM];
            float4 m1 = *(const float4*)&As[k][threadRow * TM + 4];
            float4 n0 = *(const float4*)&Bs[k][threadCol * TN];
            float4 n1 = *(const float4*)&Bs[k][threadCol * TN + 4];
            float rm[TM] = {m0.x, m0.y, m0.z, m0.w, m1.x, m1.y, m1.z, m1.w};
            float rn[TN] = {n0.x, n0.y, n0.z, n0.w, n1.x, n1.y, n1.z, n1.w};
            #pragma unroll
            for (int i = 0; i < TM; i++)
                #pragma unroll
                for (int j = 0; j < TN; j++)
                    acc[i][j] += rm[i] * rn[j];
        }
        __syncthreads();
    }

    // Epilogue
    #pragma unroll
    for (int i = 0; i < TM; i++) {
        const int r = cRow * BM + threadRow * TM + i;
        const int nbase = cCol * BN + threadCol * TN;
        if (MODE == 1) {
            #pragma unroll
            for (int j = 0; j < TN; j++)
                out[(size_t)r * N + nbase + j] = acc[i][j] + bias[nbase + j];
        } else {
            // n in [0,3072): which = n>>10 (q/k/v), head = (n&1023)>>6, d = n&63
            // 8-col chunk never crosses a 64-boundary -> which/head constant per thread
            const int b = r >> 11, t = r & 2047;
            const int which = nbase >> 10;
            const int c = nbase & 1023;
            const int h = c >> 6;
            const int dbase = c & 63;
            const int idx = (((b * NH + h) * TT + t) * HD) + dbase;
            if (which == 0) {
                #pragma unroll
                for (int j = 0; j < TN; j++)
                    g_q[idx + j] = (acc[i][j] + bias[nbase + j]) * 0.125f; // fold 1/sqrt(64)
            } else if (which == 1) {
                #pragma unroll
                for (int j = 0; j < TN; j++)
                    g_k[idx + j] = acc[i][j] + bias[nbase + j];
            } else {
                #pragma unroll
                for (int j = 0; j < TN; j++)
                    g_v[idx + j] = acc[i][j] + bias[nbase + j];
            }
        }
    }
}

// ---------------------------------------------------------------------------
// Causal flash attention, fp32 SIMT.
// grid = (32 q-tiles, 32 b*h), block = 256 (16x16 thread grid, 4x4 per thread)
// smem: Qs(16K) + KVs(16K, K then V) + Ps(16K) = 48KB static.
// Online softmax per-row state kept in registers, reduced with 16-lane shuffles.
// ---------------------------------------------------------------------------
__global__ void __launch_bounds__(256) attn_kernel()
{
    __shared__ float Qs[BQ * HD];
    __shared__ float KVs[BQ * HD];
    __shared__ float Ps[BQ * BQ];

    const int it  = blockIdx.x;     // q tile 0..31
    const int bh  = blockIdx.y;     // 0..31
    const int tid = threadIdx.x;
    const int tx  = tid & 15;       // column group (k-col / d-col)
    const int ty  = tid >> 4;       // row group (q-row)

    const float* Qg = g_q + ((size_t)bh * TT + it * BQ) * HD;

    // Q tile is one contiguous 16KB block in gmem
    #pragma unroll
    for (int i = tid; i < BQ * HD / 4; i += 256)
        ((float4*)Qs)[i] = ((const float4*)Qg)[i];

    float O[4][4];
    #pragma unroll
    for (int i = 0; i < 4; i++)
        #pragma unroll
        for (int j = 0; j < 4; j++) O[i][j] = 0.f;
    float mrow[4] = {-INFINITY, -INFINITY, -INFINITY, -INFINITY};
    float lrow[4] = {0.f, 0.f, 0.f, 0.f};

    for (int jt = 0; jt <= it; jt++) {
        __syncthreads();  // prev PV done (KVs, Ps reusable); also first-iter Q load fence
        const float* Kg = g_k + ((size_t)bh * TT + jt * BQ) * HD;
        #pragma unroll
        for (int i = tid; i < BQ * HD / 4; i += 256)
            ((float4*)KVs)[i] = ((const float4*)Kg)[i];
        __syncthreads();

        // S = (Q*scale) K^T  for this 64x64 tile; 4x4 per thread
        float s[4][4];
        #pragma unroll
        for (int i = 0; i < 4; i++)
            #pragma unroll
            for (int j = 0; j < 4; j++) s[i][j] = 0.f;
        #pragma unroll
        for (int kk = 0; kk < HD; kk += 4) {
            float4 a4[4], b4[4];
            #pragma unroll
            for (int i = 0; i < 4; i++)
                a4[i] = *(const float4*)&Qs[(4 * ty + i) * HD + kk];
            #pragma unroll
            for (int j = 0; j < 4; j++)
                b4[j] = *(const float4*)&KVs[(4 * tx + j) * HD + kk];
            #pragma unroll
            for (int i = 0; i < 4; i++)
                #pragma unroll
                for (int j = 0; j < 4; j++)
                    s[i][j] += a4[i].x * b4[j].x + a4[i].y * b4[j].y +
                               a4[i].z * b4[j].z + a4[i].w * b4[j].w;
        }

        // causal mask on the diagonal tile
        if (jt == it) {
            #pragma unroll
            for (int i = 0; i < 4; i++)
                #pragma unroll
                for (int j = 0; j < 4; j++)
                    if ((4 * tx + j) > (4 * ty + i)) s[i][j] = -INFINITY;
        }

        // Online softmax. Row r = 4*ty+i is owned by the 16 lanes sharing ty
        // (contiguous 16-lane group within a warp) -> xor-shuffles 8,4,2,1.
        #pragma unroll
        for (int i = 0; i < 4; i++) {
            float mx = fmaxf(fmaxf(s[i][0], s[i][1]), fmaxf(s[i][2], s[i][3]));
            #pragma unroll
            for (int o = 8; o >= 1; o >>= 1)
                mx = fmaxf(mx, __shfl_xor_sync(0xffffffffu, mx, o));
            float mnew = fmaxf(mrow[i], mx);
            float corr = __expf(mrow[i] - mnew);
            float p0 = __expf(s[i][0] - mnew);
            float p1 = __expf(s[i][1] - mnew);
            float p2 = __expf(s[i][2] - mnew);
            float p3 = __expf(s[i][3] - mnew);
            float sum = p0 + p1 + p2 + p3;
            #pragma unroll
            for (int o = 8; o >= 1; o >>= 1)
                sum += __shfl_xor_sync(0xffffffffu, sum, o);
            lrow[i] = lrow[i] * corr + sum;
            mrow[i] = mnew;
            #pragma unroll
            for (int j = 0; j < 4; j++) O[i][j] *= corr;
            *(float4*)&Ps[(4 * ty + i) * BQ + 4 * tx] = make_float4(p0, p1, p2, p3);
        }
        __syncthreads();  // Ps complete; all K reads done -> KVs free for V

        const float* Vg = g_v + ((size_t)bh * TT + jt * BQ) * HD;
        #pragma unroll
        for (int i = tid; i < BQ * HD / 4; i += 256)
            ((float4*)KVs)[i] = ((const float4*)Vg)[i];
        __syncthreads();

        // O += P @ V
        #pragma unroll
        for (int kk = 0; kk < BQ; kk += 4) {
            float4 p4[4], v4[4];
            #pragma unroll
            for (int i = 0; i < 4; i++)
                p4[i] = *(const float4*)&Ps[(4 * ty + i) * BQ + kk];
            #pragma unroll
            for (int k2 = 0; k2 < 4; k2++)
                v4[k2] = *(const float4*)&KVs[(kk + k2) * HD + 4 * tx];
            #pragma unroll
            for (int i = 0; i < 4; i++) {
                O[i][0] += p4[i].x * v4[0].x + p4[i].y * v4[1].x + p4[i].z * v4[2].x + p4[i].w * v4[3].x;
                O[i][1] += p4[i].x * v4[0].y + p4[i].y * v4[1].y + p4[i].z * v4[2].y + p4[i].w * v4[3].y;
                O[i][2] += p4[i].x * v4[0].z + p4[i].y * v4[1].z + p4[i].z * v4[2].z + p4[i].w * v4[3].z;
                O[i][3] += p4[i].x * v4[0].w + p4[i].y * v4[1].w + p4[i].z * v4[2].w + p4[i].w * v4[3].w;
            }
        }
    }

    // Write y in [B,T,C] layout for the proj GEMM
    const int b = bh >> 4, h = bh & 15;
    #pragma unroll
    for (int i = 0; i < 4; i++) {
        const int tq = it * BQ + 4 * ty + i;
        const float linv = 1.f / lrow[i];
        float* yp = g_y + ((size_t)b * TT + tq) * CC + h * HD + 4 * tx;
        *(float4*)yp = make_float4(O[i][0] * linv, O[i][1] * linv,
                                   O[i][2] * linv, O[i][3] * linv);
    }
}

// ---------------------------------------------------------------------------
extern "C" void kernel_launch(void* const* d_in, const int* in_sizes, int n_in,
                              void* d_out, int out_size)
{
    const float* x      = (const float*)d_in[0];  // [2,2048,1024]
    const float* w_attn = (const float*)d_in[1];  // [1024,3072]
    const float* b_attn = (const float*)d_in[2];  // [3072]
    const float* w_proj = (const float*)d_in[3];  // [1024,1024]
    const float* b_proj = (const float*)d_in[4];  // [1024]
    float* out = (float*)d_out;                   // [2,2048,1024]

    const int M = BATCH * TT;      // 4096

    // 1) QKV projection + scatter to [B,H,T,D] (q pre-scaled)
    {
        dim3 grid(3 * CC / 128, M / 128);  // (24, 32)
        sgemm_kernel<0><<<grid, 256>>>(x, w_attn, b_attn, nullptr, M, 3 * CC, CC);
    }
    // 2) Causal flash attention
    {
        dim3 grid(TT / BQ, BATCH * NH);    // (32, 32)
        attn_kernel<<<grid, 256>>>();
    }
    // 3) Output projection
    {
        dim3 grid(CC / 128, M / 128);      // (8, 32)
        sgemm_kernel<1><<<grid, 256>>>(nullptr, w_proj, b_proj, out, M, CC, CC);
    }
}